// round 1
// baseline (speedup 1.0000x reference)
#include <cuda_runtime.h>

// Deformable Conv2d: B=8, C=3, H=W=512, O=16, K=3, PAD=1, stride=1, dilation=1.
// Inputs (metadata order): x[B,C,H,W] f32, offsets[B,2*K*K,H,W] f32,
//                          weight[O,C,K,K] f32, bias[O] f32.
// Output: out[B,O,H,W] f32.

#define Bn 8
#define Cc 3
#define Hh 512
#define Ww 512
#define Oo 16
#define KK 9
#define HW (Hh * Ww)

__global__ __launch_bounds__(256) void dcn_kernel(
    const float* __restrict__ x,
    const float* __restrict__ off,
    const float* __restrict__ weight,
    const float* __restrict__ bias,
    float* __restrict__ out)
{
    __shared__ float sw[Oo * Cc * KK];  // 432 floats
    __shared__ float sb[Oo];

    int t = threadIdx.x;
    for (int i = t; i < Oo * Cc * KK; i += blockDim.x) sw[i] = weight[i];
    if (t < Oo) sb[t] = bias[t];
    __syncthreads();

    int idx = blockIdx.x * 256 + t;
    if (idx >= Bn * HW) return;

    int w = idx & (Ww - 1);
    int h = (idx >> 9) & (Hh - 1);
    int b = idx >> 18;

    const float* xb = x + (size_t)b * Cc * HW;
    const float* ob = off + (size_t)b * (2 * KK) * HW + (size_t)h * Ww + w;

    float acc[Oo];
#pragma unroll
    for (int o = 0; o < Oo; o++) acc[o] = sb[o];

#pragma unroll
    for (int k = 0; k < KK; k++) {
        const int ky = k / 3;
        const int kx = k % 3;
        float dy = __ldg(ob + (size_t)(2 * k) * HW);
        float dx = __ldg(ob + (size_t)(2 * k + 1) * HW);

        float py = dy + (float)(ky - 1 + h);
        float px = dx + (float)(kx - 1 + w);

        float y0f = floorf(py);
        float x0f = floorf(px);
        float fy = py - y0f;
        float fx = px - x0f;
        int y0 = (int)y0f;
        int x0 = (int)x0f;
        int y1 = y0 + 1;
        int x1 = x0 + 1;

        bool my0 = (y0 >= 0) && (y0 < Hh);
        bool my1 = (y1 >= 0) && (y1 < Hh);
        bool mx0 = (x0 >= 0) && (x0 < Ww);
        bool mx1 = (x1 >= 0) && (x1 < Ww);

        int cy0 = min(max(y0, 0), Hh - 1);
        int cy1 = min(max(y1, 0), Hh - 1);
        int cx0 = min(max(x0, 0), Ww - 1);
        int cx1 = min(max(x1, 0), Ww - 1);

        int o00 = cy0 * Ww + cx0;
        int o01 = cy0 * Ww + cx1;
        int o10 = cy1 * Ww + cx0;
        int o11 = cy1 * Ww + cx1;

        float w00 = (1.0f - fy) * (1.0f - fx);
        float w01 = (1.0f - fy) * fx;
        float w10 = fy * (1.0f - fx);
        float w11 = fy * fx;

        bool b00 = my0 && mx0;
        bool b01 = my0 && mx1;
        bool b10 = my1 && mx0;
        bool b11 = my1 && mx1;

#pragma unroll
        for (int c = 0; c < Cc; c++) {
            const float* p = xb + c * HW;
            float v00 = b00 ? __ldg(p + o00) : 0.0f;
            float v01 = b01 ? __ldg(p + o01) : 0.0f;
            float v10 = b10 ? __ldg(p + o10) : 0.0f;
            float v11 = b11 ? __ldg(p + o11) : 0.0f;

            float s = fmaf(w00, v00, fmaf(w01, v01, fmaf(w10, v10, w11 * v11)));

            const float* wk = sw + c * KK + k;
#pragma unroll
            for (int o = 0; o < Oo; o++) {
                acc[o] = fmaf(s, wk[o * Cc * KK], acc[o]);
            }
        }
    }

    float* ot = out + (size_t)b * Oo * HW + (size_t)h * Ww + w;
#pragma unroll
    for (int o = 0; o < Oo; o++) {
        ot[(size_t)o * HW] = acc[o];
    }
}

extern "C" void kernel_launch(void* const* d_in, const int* in_sizes, int n_in,
                              void* d_out, int out_size)
{
    const float* x      = (const float*)d_in[0];
    const float* off    = (const float*)d_in[1];
    const float* weight = (const float*)d_in[2];
    const float* bias   = (const float*)d_in[3];
    float* out          = (float*)d_out;

    int total = Bn * HW;
    int blocks = (total + 255) / 256;
    dcn_kernel<<<blocks, 256>>>(x, off, weight, bias, out);
}

// round 2
// speedup vs baseline: 1.1526x; 1.1526x over previous
#include <cuda_runtime.h>

// Deformable Conv2d: B=8, C=3, H=W=512, O=16, K=3, PAD=1.
// Each thread computes 2 vertically-adjacent output pixels (rows h, h+1),
// all 16 output channels. Weights staged in smem as [k][c][o] for float4 reads.

#define Bn 8
#define Cc 3
#define Hh 512
#define Ww 512
#define Oo 16
#define KK 9
#define HW (Hh * Ww)

__global__ __launch_bounds__(256) void dcn_kernel(
    const float* __restrict__ x,
    const float* __restrict__ off,
    const float* __restrict__ weight,
    const float* __restrict__ bias,
    float* __restrict__ out)
{
    __shared__ float swt[KK * Cc * Oo];  // [k][c][o], 432 floats
    __shared__ float sb[Oo];

    int t = threadIdx.x;
    for (int i = t; i < KK * Cc * Oo; i += blockDim.x) {
        int k = i / (Cc * Oo);
        int r = i % (Cc * Oo);
        int c = r / Oo;
        int o = r % Oo;
        swt[i] = weight[o * (Cc * KK) + c * KK + k];
    }
    if (t < Oo) sb[t] = bias[t];
    __syncthreads();

    // thread -> (b, h-pair, w)
    int idx = blockIdx.x * 256 + t;          // 0 .. B*(H/2)*W - 1  (exactly 1M, grid exact)
    int w  = idx & (Ww - 1);
    int hp = (idx >> 9) & (Hh / 2 - 1);
    int b  = idx >> 17;
    int h  = hp * 2;

    const float* xb  = x + (size_t)b * Cc * HW;
    const float* ob  = off + (size_t)b * (2 * KK) * HW + (size_t)h * Ww + w;

    float acc0[Oo], acc1[Oo];
#pragma unroll
    for (int o = 0; o < Oo; o++) { acc0[o] = sb[o]; acc1[o] = sb[o]; }

#pragma unroll
    for (int k = 0; k < KK; k++) {
        const int ky = k / 3;
        const int kx = k % 3;

        // offsets for both rows
        float dy0 = __ldg(ob + (size_t)(2 * k) * HW);
        float dx0 = __ldg(ob + (size_t)(2 * k + 1) * HW);
        float dy1 = __ldg(ob + (size_t)(2 * k) * HW + Ww);
        float dx1 = __ldg(ob + (size_t)(2 * k + 1) * HW + Ww);

        // --- pixel 0 (row h) coords ---
        float py0 = dy0 + (float)(ky - 1 + h);
        float px0 = dx0 + (float)(kx - 1 + w);
        float y0f0 = floorf(py0), x0f0 = floorf(px0);
        float fy0 = py0 - y0f0,  fx0 = px0 - x0f0;
        int ya0 = (int)y0f0, xa0 = (int)x0f0;
        int yb0 = ya0 + 1,   xb0 = xa0 + 1;
        bool mya0 = (ya0 >= 0) & (ya0 < Hh), myb0 = (yb0 >= 0) & (yb0 < Hh);
        bool mxa0 = (xa0 >= 0) & (xa0 < Ww), mxb0 = (xb0 >= 0) & (xb0 < Ww);
        int cya0 = min(max(ya0, 0), Hh - 1), cyb0 = min(max(yb0, 0), Hh - 1);
        int cxa0 = min(max(xa0, 0), Ww - 1), cxb0 = min(max(xb0, 0), Ww - 1);
        int p000 = cya0 * Ww + cxa0, p001 = cya0 * Ww + cxb0;
        int p010 = cyb0 * Ww + cxa0, p011 = cyb0 * Ww + cxb0;
        float w000 = (1.f - fy0) * (1.f - fx0), w001 = (1.f - fy0) * fx0;
        float w010 = fy0 * (1.f - fx0),         w011 = fy0 * fx0;
        bool g000 = mya0 & mxa0, g001 = mya0 & mxb0;
        bool g010 = myb0 & mxa0, g011 = myb0 & mxb0;

        // --- pixel 1 (row h+1) coords ---
        float py1 = dy1 + (float)(ky + h);      // ky - 1 + (h+1)
        float px1 = dx1 + (float)(kx - 1 + w);
        float y0f1 = floorf(py1), x0f1 = floorf(px1);
        float fy1 = py1 - y0f1,  fx1 = px1 - x0f1;
        int ya1 = (int)y0f1, xa1 = (int)x0f1;
        int yb1 = ya1 + 1,   xb1 = xa1 + 1;
        bool mya1 = (ya1 >= 0) & (ya1 < Hh), myb1 = (yb1 >= 0) & (yb1 < Hh);
        bool mxa1 = (xa1 >= 0) & (xa1 < Ww), mxb1 = (xb1 >= 0) & (xb1 < Ww);
        int cya1 = min(max(ya1, 0), Hh - 1), cyb1 = min(max(yb1, 0), Hh - 1);
        int cxa1 = min(max(xa1, 0), Ww - 1), cxb1 = min(max(xb1, 0), Ww - 1);
        int p100 = cya1 * Ww + cxa1, p101 = cya1 * Ww + cxb1;
        int p110 = cyb1 * Ww + cxa1, p111 = cyb1 * Ww + cxb1;
        float w100 = (1.f - fy1) * (1.f - fx1), w101 = (1.f - fy1) * fx1;
        float w110 = fy1 * (1.f - fx1),         w111 = fy1 * fx1;
        bool g100 = mya1 & mxa1, g101 = mya1 & mxb1;
        bool g110 = myb1 & mxa1, g111 = myb1 & mxb1;

#pragma unroll
        for (int c = 0; c < Cc; c++) {
            const float* p = xb + c * HW;
            float v000 = g000 ? __ldg(p + p000) : 0.f;
            float v001 = g001 ? __ldg(p + p001) : 0.f;
            float v010 = g010 ? __ldg(p + p010) : 0.f;
            float v011 = g011 ? __ldg(p + p011) : 0.f;
            float v100 = g100 ? __ldg(p + p100) : 0.f;
            float v101 = g101 ? __ldg(p + p101) : 0.f;
            float v110 = g110 ? __ldg(p + p110) : 0.f;
            float v111 = g111 ? __ldg(p + p111) : 0.f;

            float s0 = fmaf(w000, v000, fmaf(w001, v001, fmaf(w010, v010, w011 * v011)));
            float s1 = fmaf(w100, v100, fmaf(w101, v101, fmaf(w110, v110, w111 * v111)));

            const float4* wv = (const float4*)(swt + (k * Cc + c) * Oo);
#pragma unroll
            for (int j = 0; j < 4; j++) {
                float4 wq = wv[j];
                acc0[j * 4 + 0] = fmaf(s0, wq.x, acc0[j * 4 + 0]);
                acc0[j * 4 + 1] = fmaf(s0, wq.y, acc0[j * 4 + 1]);
                acc0[j * 4 + 2] = fmaf(s0, wq.z, acc0[j * 4 + 2]);
                acc0[j * 4 + 3] = fmaf(s0, wq.w, acc0[j * 4 + 3]);
                acc1[j * 4 + 0] = fmaf(s1, wq.x, acc1[j * 4 + 0]);
                acc1[j * 4 + 1] = fmaf(s1, wq.y, acc1[j * 4 + 1]);
                acc1[j * 4 + 2] = fmaf(s1, wq.z, acc1[j * 4 + 2]);
                acc1[j * 4 + 3] = fmaf(s1, wq.w, acc1[j * 4 + 3]);
            }
        }
    }

    float* ot = out + (size_t)b * Oo * HW + (size_t)h * Ww + w;
#pragma unroll
    for (int o = 0; o < Oo; o++) {
        ot[(size_t)o * HW] = acc0[o];
        ot[(size_t)o * HW + Ww] = acc1[o];
    }
}

extern "C" void kernel_launch(void* const* d_in, const int* in_sizes, int n_in,
                              void* d_out, int out_size)
{
    const float* x      = (const float*)d_in[0];
    const float* off    = (const float*)d_in[1];
    const float* weight = (const float*)d_in[2];
    const float* bias   = (const float*)d_in[3];
    float* out          = (float*)d_out;

    int total = Bn * (Hh / 2) * Ww;          // 1,048,576
    int blocks = total / 256;                // 4096
    dcn_kernel<<<blocks, 256>>>(x, off, weight, bias, out);
}

// round 3
// speedup vs baseline: 1.3912x; 1.2070x over previous
#include <cuda_runtime.h>

// Deformable Conv2d: B=8, C=3, H=W=512, O=16, K=3, PAD=1.
// Two-kernel plan:
//   1) repack x NCHW -> NHWC float4 (c0,c1,c2,0) in __device__ scratch
//   2) main kernel: 1 pixel/thread, each bilinear corner = one LDG.128

#define Bn 8
#define Cc 3
#define Hh 512
#define Ww 512
#define Oo 16
#define KK 9
#define HW (Hh * Ww)

__device__ float4 g_xt[Bn * HW];   // 33.5 MB scratch, NHWC-packed

__global__ __launch_bounds__(256) void repack_kernel(const float* __restrict__ x)
{
    int i = blockIdx.x * 256 + threadIdx.x;      // 0 .. Bn*HW-1 (exact grid)
    int b = i >> 18;
    int p = i & (HW - 1);
    const float* xb = x + (size_t)b * Cc * HW + p;
    g_xt[i] = make_float4(xb[0], xb[HW], xb[2 * HW], 0.0f);
}

__global__ __launch_bounds__(256, 4) void dcn_kernel(
    const float* __restrict__ off,
    const float* __restrict__ weight,
    const float* __restrict__ bias,
    float* __restrict__ out)
{
    __shared__ float swt[KK * Cc * Oo];  // [k][c][o]
    __shared__ float sb[Oo];

    int t = threadIdx.x;
    for (int i = t; i < KK * Cc * Oo; i += 256) {
        int k = i / (Cc * Oo);
        int r = i % (Cc * Oo);
        int c = r / Oo;
        int o = r % Oo;
        swt[i] = weight[o * (Cc * KK) + c * KK + k];
    }
    if (t < Oo) sb[t] = bias[t];
    __syncthreads();

    int idx = blockIdx.x * 256 + t;              // 0 .. Bn*HW-1 (exact grid)
    int w = idx & (Ww - 1);
    int h = (idx >> 9) & (Hh - 1);
    int b = idx >> 18;

    const float4* xtb = g_xt + (size_t)b * HW;
    const float* ob = off + (size_t)b * (2 * KK) * HW + (size_t)h * Ww + w;

    float acc[Oo];
#pragma unroll
    for (int o = 0; o < Oo; o++) acc[o] = sb[o];

#pragma unroll
    for (int k = 0; k < KK; k++) {
        const int ky = k / 3;
        const int kx = k % 3;
        float dy = __ldg(ob + (size_t)(2 * k) * HW);
        float dx = __ldg(ob + (size_t)(2 * k + 1) * HW);

        float py = dy + (float)(ky - 1 + h);
        float px = dx + (float)(kx - 1 + w);

        float y0f = floorf(py);
        float x0f = floorf(px);
        float fy = py - y0f;
        float fx = px - x0f;
        int y0 = (int)y0f;
        int x0 = (int)x0f;
        int y1 = y0 + 1;
        int x1 = x0 + 1;

        bool my0 = (y0 >= 0) & (y0 < Hh);
        bool my1 = (y1 >= 0) & (y1 < Hh);
        bool mx0 = (x0 >= 0) & (x0 < Ww);
        bool mx1 = (x1 >= 0) & (x1 < Ww);

        int cy0 = min(max(y0, 0), Hh - 1);
        int cy1 = min(max(y1, 0), Hh - 1);
        int cx0 = min(max(x0, 0), Ww - 1);
        int cx1 = min(max(x1, 0), Ww - 1);

        int o00 = cy0 * Ww + cx0;
        int o01 = cy0 * Ww + cx1;
        int o10 = cy1 * Ww + cx0;
        int o11 = cy1 * Ww + cx1;

        float w00 = (1.0f - fy) * (1.0f - fx);
        float w01 = (1.0f - fy) * fx;
        float w10 = fy * (1.0f - fx);
        float w11 = fy * fx;

        float4 z = make_float4(0.f, 0.f, 0.f, 0.f);
        float4 v00 = (my0 & mx0) ? __ldg(xtb + o00) : z;
        float4 v01 = (my0 & mx1) ? __ldg(xtb + o01) : z;
        float4 v10 = (my1 & mx0) ? __ldg(xtb + o10) : z;
        float4 v11 = (my1 & mx1) ? __ldg(xtb + o11) : z;

        // bilinear blend per channel
        float s0 = fmaf(w00, v00.x, fmaf(w01, v01.x, fmaf(w10, v10.x, w11 * v11.x)));
        float s1 = fmaf(w00, v00.y, fmaf(w01, v01.y, fmaf(w10, v10.y, w11 * v11.y)));
        float s2 = fmaf(w00, v00.z, fmaf(w01, v01.z, fmaf(w10, v10.z, w11 * v11.z)));

        const float4* wv0 = (const float4*)(swt + (k * Cc + 0) * Oo);
        const float4* wv1 = (const float4*)(swt + (k * Cc + 1) * Oo);
        const float4* wv2 = (const float4*)(swt + (k * Cc + 2) * Oo);
#pragma unroll
        for (int j = 0; j < 4; j++) {
            float4 q0 = wv0[j];
            float4 q1 = wv1[j];
            float4 q2 = wv2[j];
            acc[j * 4 + 0] = fmaf(s0, q0.x, fmaf(s1, q1.x, fmaf(s2, q2.x, acc[j * 4 + 0])));
            acc[j * 4 + 1] = fmaf(s0, q0.y, fmaf(s1, q1.y, fmaf(s2, q2.y, acc[j * 4 + 1])));
            acc[j * 4 + 2] = fmaf(s0, q0.z, fmaf(s1, q1.z, fmaf(s2, q2.z, acc[j * 4 + 2])));
            acc[j * 4 + 3] = fmaf(s0, q0.w, fmaf(s1, q1.w, fmaf(s2, q2.w, acc[j * 4 + 3])));
        }
    }

    float* ot = out + (size_t)b * Oo * HW + (size_t)h * Ww + w;
#pragma unroll
    for (int o = 0; o < Oo; o++) {
        ot[(size_t)o * HW] = acc[o];
    }
}

extern "C" void kernel_launch(void* const* d_in, const int* in_sizes, int n_in,
                              void* d_out, int out_size)
{
    const float* x      = (const float*)d_in[0];
    const float* off    = (const float*)d_in[1];
    const float* weight = (const float*)d_in[2];
    const float* bias   = (const float*)d_in[3];
    float* out          = (float*)d_out;

    int total = Bn * HW;                 // 2,097,152
    repack_kernel<<<total / 256, 256>>>(x);
    dcn_kernel<<<total / 256, 256>>>(off, weight, bias, out);
}

// round 4
// speedup vs baseline: 1.7497x; 1.2577x over previous
#include <cuda_runtime.h>
#include <cuda_fp16.h>

// Deformable Conv2d: B=8, C=3, H=W=512, O=16, K=3, PAD=1.
//  1) repack x NCHW f32 -> NHWC fp16x4 (c0,c1,c2,0) in __device__ scratch
//  2) weights+bias in __constant__ (LDC path, off L1tex)
//  3) main kernel: 1 pixel/thread, each bilinear corner = one LDG.64

#define Bn 8
#define Cc 3
#define Hh 512
#define Ww 512
#define Oo 16
#define KK 9
#define HW (Hh * Ww)

__device__ uint2 g_xh[Bn * HW];            // 16.8 MB: 4 halves per pixel
__constant__ float cw[Oo * Cc * KK];       // [o][c][k] as in input layout
__constant__ float cb[Oo];

__global__ __launch_bounds__(256) void repack_kernel(const float* __restrict__ x)
{
    int i = blockIdx.x * 256 + threadIdx.x;      // exact grid
    int b = i >> 18;
    int p = i & (HW - 1);
    const float* xb = x + (size_t)b * Cc * HW + p;
    __half2 h01 = __floats2half2_rn(xb[0], xb[HW]);
    __half2 h23 = __floats2half2_rn(xb[2 * HW], 0.0f);
    uint2 u;
    u.x = *reinterpret_cast<unsigned int*>(&h01);
    u.y = *reinterpret_cast<unsigned int*>(&h23);
    g_xh[i] = u;
}

__global__ __launch_bounds__(256, 4) void dcn_kernel(
    const float* __restrict__ off,
    float* __restrict__ out)
{
    int idx = blockIdx.x * 256 + threadIdx.x;    // exact grid
    int w = idx & (Ww - 1);
    int h = (idx >> 9) & (Hh - 1);
    int b = idx >> 18;

    const uint2* xtb = g_xh + (size_t)b * HW;
    const float* ob = off + (size_t)b * (2 * KK) * HW + (size_t)h * Ww + w;

    float acc[Oo];
#pragma unroll
    for (int o = 0; o < Oo; o++) acc[o] = cb[o];

#pragma unroll
    for (int k = 0; k < KK; k++) {
        const int ky = k / 3;
        const int kx = k % 3;
        float dy = __ldg(ob + (size_t)(2 * k) * HW);
        float dx = __ldg(ob + (size_t)(2 * k + 1) * HW);

        float py = dy + (float)(ky - 1 + h);
        float px = dx + (float)(kx - 1 + w);

        float y0f = floorf(py);
        float x0f = floorf(px);
        float fy = py - y0f;
        float fx = px - x0f;
        int y0 = (int)y0f;
        int x0 = (int)x0f;
        int y1 = y0 + 1;
        int x1 = x0 + 1;

        bool my0 = (y0 >= 0) & (y0 < Hh);
        bool my1 = (y1 >= 0) & (y1 < Hh);
        bool mx0 = (x0 >= 0) & (x0 < Ww);
        bool mx1 = (x1 >= 0) & (x1 < Ww);

        int cy0 = min(max(y0, 0), Hh - 1);
        int cy1 = min(max(y1, 0), Hh - 1);
        int cx0 = min(max(x0, 0), Ww - 1);
        int cx1 = min(max(x1, 0), Ww - 1);

        int o00 = cy0 * Ww + cx0;
        int o01 = cy0 * Ww + cx1;
        int o10 = cy1 * Ww + cx0;
        int o11 = cy1 * Ww + cx1;

        float w00 = (1.0f - fy) * (1.0f - fx);
        float w01 = (1.0f - fy) * fx;
        float w10 = fy * (1.0f - fx);
        float w11 = fy * fx;

        uint2 z = make_uint2(0u, 0u);
        uint2 u00 = (my0 & mx0) ? __ldg(xtb + o00) : z;
        uint2 u01 = (my0 & mx1) ? __ldg(xtb + o01) : z;
        uint2 u10 = (my1 & mx0) ? __ldg(xtb + o10) : z;
        uint2 u11 = (my1 & mx1) ? __ldg(xtb + o11) : z;

        float2 a00 = __half22float2(*reinterpret_cast<__half2*>(&u00.x));
        float2 b00f = __half22float2(*reinterpret_cast<__half2*>(&u00.y));
        float2 a01 = __half22float2(*reinterpret_cast<__half2*>(&u01.x));
        float2 b01f = __half22float2(*reinterpret_cast<__half2*>(&u01.y));
        float2 a10 = __half22float2(*reinterpret_cast<__half2*>(&u10.x));
        float2 b10f = __half22float2(*reinterpret_cast<__half2*>(&u10.y));
        float2 a11 = __half22float2(*reinterpret_cast<__half2*>(&u11.x));
        float2 b11f = __half22float2(*reinterpret_cast<__half2*>(&u11.y));

        float s0 = fmaf(w00, a00.x, fmaf(w01, a01.x, fmaf(w10, a10.x, w11 * a11.x)));
        float s1 = fmaf(w00, a00.y, fmaf(w01, a01.y, fmaf(w10, a10.y, w11 * a11.y)));
        float s2 = fmaf(w00, b00f.x, fmaf(w01, b01f.x, fmaf(w10, b10f.x, w11 * b11f.x)));

#pragma unroll
        for (int o = 0; o < Oo; o++) {
            acc[o] = fmaf(s0, cw[o * (Cc * KK) + 0 * KK + k],
                     fmaf(s1, cw[o * (Cc * KK) + 1 * KK + k],
                     fmaf(s2, cw[o * (Cc * KK) + 2 * KK + k], acc[o])));
        }
    }

    float* ot = out + (size_t)b * Oo * HW + (size_t)h * Ww + w;
#pragma unroll
    for (int o = 0; o < Oo; o++) {
        ot[(size_t)o * HW] = acc[o];
    }
}

extern "C" void kernel_launch(void* const* d_in, const int* in_sizes, int n_in,
                              void* d_out, int out_size)
{
    const float* x      = (const float*)d_in[0];
    const float* off    = (const float*)d_in[1];
    const float* weight = (const float*)d_in[2];
    const float* bias   = (const float*)d_in[3];
    float* out          = (float*)d_out;

    cudaMemcpyToSymbolAsync(cw, weight, Oo * Cc * KK * sizeof(float), 0,
                            cudaMemcpyDeviceToDevice);
    cudaMemcpyToSymbolAsync(cb, bias, Oo * sizeof(float), 0,
                            cudaMemcpyDeviceToDevice);

    int total = Bn * HW;                 // 2,097,152
    repack_kernel<<<total / 256, 256>>>(x);
    dcn_kernel<<<total / 256, 256>>>(off, out);
}

// round 6
// speedup vs baseline: 2.3124x; 1.3216x over previous
#include <cuda_runtime.h>
#include <cuda_fp16.h>

// Deformable Conv2d: B=8, C=3, H=W=512, O=16, K=3, PAD=1.
//  - x repacked NCHW f32 -> zero-padded NHWC fp16x4 (515 rows x 516 stride)
//    so all bilinear corner gathers are unconditional LDG.64 (no bounds logic)
//  - weights pre-paired into 64-bit f32x2 constants; 16x27 contraction done
//    with fma.rn.f32x2 (Blackwell packed dual-FP32 FMA) -> half the FMA issues
//  - R5 fix: source address for symbol->symbol copies resolved via
//    cudaGetSymbolAddress (passing the __device__ symbol directly as src was
//    the host shadow pointer -> garbage constants).

#define Bn 8
#define Cc 3
#define Hh 512
#define Ww 512
#define Oo 16
#define KK 9
#define HW (Hh * Ww)

#define PROWS 515            // padded coords: 0..514
#define PSTRIDE 516
#define PTOT (PROWS * PSTRIDE)

__device__ uint2 g_xh[Bn * PTOT];                    // padded fp16x4 image
__device__ unsigned long long g_wpack[KK * Cc * 8];  // [k][c][opair]
__device__ unsigned long long g_bpack[8];

__constant__ unsigned long long cwp[KK * Cc * 8];
__constant__ unsigned long long cbp[8];

__global__ void prep_weights(const float* __restrict__ weight,
                             const float* __restrict__ bias)
{
    int i = threadIdx.x;                 // 0..255
    if (i < KK * Cc * 8) {
        int k = i / (Cc * 8);
        int r = i % (Cc * 8);
        int c = r / 8;
        int j = r % 8;
        float w0 = weight[(2 * j + 0) * (Cc * KK) + c * KK + k];
        float w1 = weight[(2 * j + 1) * (Cc * KK) + c * KK + k];
        unsigned long long u;
        asm("mov.b64 %0, {%1, %2};" : "=l"(u) : "f"(w0), "f"(w1));
        g_wpack[i] = u;
    }
    if (i < 8) {
        unsigned long long u;
        asm("mov.b64 %0, {%1, %2};" : "=l"(u) : "f"(bias[2 * i]), "f"(bias[2 * i + 1]));
        g_bpack[i] = u;
    }
}

__global__ __launch_bounds__(256) void repack_kernel(const float* __restrict__ x)
{
    int i = blockIdx.x * 256 + threadIdx.x;
    if (i >= Bn * PTOT) return;
    int b = i / PTOT;
    int p = i % PTOT;
    int yy = p / PSTRIDE;
    int xx = p % PSTRIDE;

    uint2 u = make_uint2(0u, 0u);
    if (yy >= 1 && yy <= Hh && xx >= 1 && xx <= Ww) {
        const float* xb = x + (size_t)b * Cc * HW + (size_t)(yy - 1) * Ww + (xx - 1);
        __half2 h01 = __floats2half2_rn(xb[0], xb[HW]);
        __half2 h23 = __floats2half2_rn(xb[2 * HW], 0.0f);
        u.x = *reinterpret_cast<unsigned int*>(&h01);
        u.y = *reinterpret_cast<unsigned int*>(&h23);
    }
    g_xh[i] = u;
}

__device__ __forceinline__ unsigned long long pack2(float v)
{
    unsigned long long u;
    asm("mov.b64 %0, {%1, %1};" : "=l"(u) : "f"(v));
    return u;
}

__global__ __launch_bounds__(256, 4) void dcn_kernel(
    const float* __restrict__ off,
    float* __restrict__ out)
{
    int idx = blockIdx.x * 256 + threadIdx.x;    // exact grid
    int w = idx & (Ww - 1);
    int h = (idx >> 9) & (Hh - 1);
    int b = idx >> 18;

    const uint2* xtb = g_xh + (size_t)b * PTOT;
    const float* ob = off + (size_t)b * (2 * KK) * HW + (size_t)h * Ww + w;

    unsigned long long accp[8];
#pragma unroll
    for (int j = 0; j < 8; j++) accp[j] = cbp[j];

#pragma unroll
    for (int k = 0; k < KK; k++) {
        const int ky = k / 3;
        const int kx = k % 3;
        float dy = __ldg(ob + (size_t)(2 * k) * HW);
        float dx = __ldg(ob + (size_t)(2 * k + 1) * HW);

        float py = dy + (float)(ky - 1 + h);
        float px = dx + (float)(kx - 1 + w);

        // clamp to [-1, 512]: identical result (border/weight-0), enables
        // unconditional padded gathers
        py = fminf(fmaxf(py, -1.0f), 512.0f);
        px = fminf(fmaxf(px, -1.0f), 512.0f);

        float y0f = floorf(py);
        float x0f = floorf(px);
        float fy = py - y0f;
        float fx = px - x0f;
        int y0 = (int)y0f;
        int x0 = (int)x0f;

        int base = (y0 + 1) * PSTRIDE + (x0 + 1);

        uint2 u00 = __ldg(xtb + base);
        uint2 u01 = __ldg(xtb + base + 1);
        uint2 u10 = __ldg(xtb + base + PSTRIDE);
        uint2 u11 = __ldg(xtb + base + PSTRIDE + 1);

        float w00 = (1.0f - fy) * (1.0f - fx);
        float w01 = (1.0f - fy) * fx;
        float w10 = fy * (1.0f - fx);
        float w11 = fy * fx;

        float2 a00 = __half22float2(*reinterpret_cast<__half2*>(&u00.x));
        float2 c00 = __half22float2(*reinterpret_cast<__half2*>(&u00.y));
        float2 a01 = __half22float2(*reinterpret_cast<__half2*>(&u01.x));
        float2 c01 = __half22float2(*reinterpret_cast<__half2*>(&u01.y));
        float2 a10 = __half22float2(*reinterpret_cast<__half2*>(&u10.x));
        float2 c10 = __half22float2(*reinterpret_cast<__half2*>(&u10.y));
        float2 a11 = __half22float2(*reinterpret_cast<__half2*>(&u11.x));
        float2 c11 = __half22float2(*reinterpret_cast<__half2*>(&u11.y));

        float s0 = fmaf(w00, a00.x, fmaf(w01, a01.x, fmaf(w10, a10.x, w11 * a11.x)));
        float s1 = fmaf(w00, a00.y, fmaf(w01, a01.y, fmaf(w10, a10.y, w11 * a11.y)));
        float s2 = fmaf(w00, c00.x, fmaf(w01, c01.x, fmaf(w10, c10.x, w11 * c11.x)));

        unsigned long long sp0 = pack2(s0);
        unsigned long long sp1 = pack2(s1);
        unsigned long long sp2 = pack2(s2);

#pragma unroll
        for (int j = 0; j < 8; j++) {
            asm("fma.rn.f32x2 %0, %1, %2, %0;"
                : "+l"(accp[j]) : "l"(sp0), "l"(cwp[(k * Cc + 0) * 8 + j]));
            asm("fma.rn.f32x2 %0, %1, %2, %0;"
                : "+l"(accp[j]) : "l"(sp1), "l"(cwp[(k * Cc + 1) * 8 + j]));
            asm("fma.rn.f32x2 %0, %1, %2, %0;"
                : "+l"(accp[j]) : "l"(sp2), "l"(cwp[(k * Cc + 2) * 8 + j]));
        }
    }

    float* ot = out + (size_t)b * Oo * HW + (size_t)h * Ww + w;
#pragma unroll
    for (int j = 0; j < 8; j++) {
        float lo, hi;
        asm("mov.b64 {%0, %1}, %2;" : "=f"(lo), "=f"(hi) : "l"(accp[j]));
        ot[(size_t)(2 * j + 0) * HW] = lo;
        ot[(size_t)(2 * j + 1) * HW] = hi;
    }
}

extern "C" void kernel_launch(void* const* d_in, const int* in_sizes, int n_in,
                              void* d_out, int out_size)
{
    const float* x      = (const float*)d_in[0];
    const float* off    = (const float*)d_in[1];
    const float* weight = (const float*)d_in[2];
    const float* bias   = (const float*)d_in[3];
    float* out          = (float*)d_out;

    prep_weights<<<1, 256>>>(weight, bias);

    // Resolve real device addresses of the __device__ staging arrays.
    void* wsrc = nullptr;
    void* bsrc = nullptr;
    cudaGetSymbolAddress(&wsrc, g_wpack);
    cudaGetSymbolAddress(&bsrc, g_bpack);
    cudaMemcpyToSymbolAsync(cwp, wsrc, KK * Cc * 8 * sizeof(unsigned long long),
                            0, cudaMemcpyDeviceToDevice);
    cudaMemcpyToSymbolAsync(cbp, bsrc, 8 * sizeof(unsigned long long),
                            0, cudaMemcpyDeviceToDevice);

    int ptotal = Bn * PTOT;
    repack_kernel<<<(ptotal + 255) / 256, 256>>>(x);

    int total = Bn * HW;                 // 2,097,152
    dcn_kernel<<<total / 256, 256>>>(off, out);
}